// round 1
// baseline (speedup 1.0000x reference)
#include <cuda_runtime.h>

// TrajectoryScore: 64 segments x 100000 obs. Streaming HBM-bound reduction.
// out[0:64)   = log_like per segment
// out[64:128) = hits per segment
// out[128:192)= hits_raw (== hits)

#define SEGS     64
#define NPER     100000
#define GROUPS   (NPER / 4)      // 25000 groups of 4 rows
#define THREADS  256
#define BPS      16              // blocks per segment

__global__ void zero_out_kernel(float* out) {
    int i = blockIdx.x * blockDim.x + threadIdx.x;
    if (i < 3 * SEGS) out[i] = 0.0f;
}

__global__ __launch_bounds__(THREADS)
void trajectory_score_kernel(const float* __restrict__ u_pred,
                             const float* __restrict__ u_obs,
                             const float* __restrict__ h,
                             const float* __restrict__ lam,
                             const float* __restrict__ thresh,
                             float* __restrict__ out) {
    const int seg = blockIdx.y;

    // Per-segment constants in registers
    const float hs   = __ldg(h + seg);
    const float ls   = __ldg(lam + seg);
    const float ts   = __ldg(thresh + seg);
    const float invt = __frcp_rn(ts);
    // p_hit = h * lam/(1-exp(-lam)) * exp(-lam*v)  -> fold h into c
    const float c    = hs * ls * __frcp_rn(1.0f - __expf(-ls));
    const float omh  = 1.0f - hs;
    const float neg_ls_invt = -ls * invt;   // exponent = neg_ls_invt * s2

    // Segment base: 100000 rows * 3 floats = 300000 floats = 75000 float4 (16B aligned)
    const float4* __restrict__ p4 =
        reinterpret_cast<const float4*>(u_pred) + (size_t)seg * (NPER * 3 / 4);
    const float4* __restrict__ o4 =
        reinterpret_cast<const float4*>(u_obs) + (size_t)seg * (NPER * 3 / 4);

    float slog = 0.0f;
    float shit = 0.0f;

    for (int g = blockIdx.x * THREADS + threadIdx.x; g < GROUPS; g += BPS * THREADS) {
        // 4 rows = 12 floats = 3 float4 from each tensor (6 independent LDG.128)
        const float4 pa = __ldg(p4 + 3 * g + 0);
        const float4 pb = __ldg(p4 + 3 * g + 1);
        const float4 pc = __ldg(p4 + 3 * g + 2);
        const float4 oa = __ldg(o4 + 3 * g + 0);
        const float4 ob = __ldg(o4 + 3 * g + 1);
        const float4 oc = __ldg(o4 + 3 * g + 2);

        float s2[4];
        {
            float dx = pa.x - oa.x, dy = pa.y - oa.y, dz = pa.z - oa.z;
            s2[0] = dx * dx + dy * dy + dz * dz;
        }
        {
            float dx = pa.w - oa.w, dy = pb.x - ob.x, dz = pb.y - ob.y;
            s2[1] = dx * dx + dy * dy + dz * dz;
        }
        {
            float dx = pb.z - ob.z, dy = pb.w - ob.w, dz = pc.x - oc.x;
            s2[2] = dx * dx + dy * dy + dz * dz;
        }
        {
            float dx = pc.y - oc.y, dy = pc.z - oc.z, dz = pc.w - oc.w;
            s2[3] = dx * dx + dy * dy + dz * dz;
        }

#pragma unroll
        for (int k = 0; k < 4; ++k) {
            const float s = s2[k];
            if (s < ts) {
                const float ph   = c * __expf(neg_ls_invt * s);
                const float p    = ph + omh;
                slog += __logf(p);
                const float post = __fdividef(ph, p);
                if (post > 0.95f) shit += post;
            }
        }
    }

    // Warp reduce
#pragma unroll
    for (int off = 16; off > 0; off >>= 1) {
        slog += __shfl_down_sync(0xFFFFFFFFu, slog, off);
        shit += __shfl_down_sync(0xFFFFFFFFu, shit, off);
    }

    __shared__ float sl[THREADS / 32];
    __shared__ float sh[THREADS / 32];
    const int lane = threadIdx.x & 31;
    const int wid  = threadIdx.x >> 5;
    if (lane == 0) { sl[wid] = slog; sh[wid] = shit; }
    __syncthreads();

    if (threadIdx.x == 0) {
        float a = 0.0f, b = 0.0f;
#pragma unroll
        for (int i = 0; i < THREADS / 32; ++i) { a += sl[i]; b += sh[i]; }
        atomicAdd(out + seg,            a);
        atomicAdd(out + SEGS + seg,     b);
        atomicAdd(out + 2 * SEGS + seg, b);
    }
}

extern "C" void kernel_launch(void* const* d_in, const int* in_sizes, int n_in,
                              void* d_out, int out_size) {
    const float* u_pred = (const float*)d_in[0];
    const float* u_obs  = (const float*)d_in[1];
    const float* h      = (const float*)d_in[2];
    const float* lam    = (const float*)d_in[3];
    const float* thresh = (const float*)d_in[4];
    float* out = (float*)d_out;

    zero_out_kernel<<<1, 3 * SEGS>>>(out);
    dim3 grid(BPS, SEGS);
    trajectory_score_kernel<<<grid, THREADS>>>(u_pred, u_obs, h, lam, thresh, out);
}

// round 3
// speedup vs baseline: 1.0650x; 1.0650x over previous
#include <cuda_runtime.h>

// TrajectoryScore: 64 segments x 100000 obs (contiguous). Streaming HBM-bound.
// out[0:64) = log_like, out[64:128) = hits, out[128:192) = hits_raw (== hits).
//
// Single kernel launch:
//  - 888 = 148*6 blocks, each owning a contiguous equal slice of the global
//    4-row-group index space (straddles at most one segment boundary).
//  - per-block partials -> __device__ accumulators (atomicAdd)
//  - last block (ticket) writes d_out and resets state (graph-replay safe).

#define SEGS    64
#define GPS     25000            // 4-row groups per segment (100000 rows / 4)
#define GTOT    (SEGS * GPS)     // 1,600,000 groups
#define THREADS 256
#define NBLK    888              // 148 SMs * 6 CTAs
#define QW      (GTOT / NBLK)    // 1801
#define RW      (GTOT - NBLK * QW) // 712 blocks get one extra group

__device__ float        g_acc[2 * SEGS];   // [log_like | hits], zero-init at load
__device__ unsigned int g_done;            // zero-init at load

__global__ __launch_bounds__(THREADS, 6)
void trajectory_score_kernel(const float* __restrict__ u_pred,
                             const float* __restrict__ u_obs,
                             const float* __restrict__ h,
                             const float* __restrict__ lam,
                             const float* __restrict__ thresh,
                             float* __restrict__ out) {
    const int b   = blockIdx.x;
    const int tid = threadIdx.x;

    // Balanced contiguous split of [0, GTOT)
    const int g0 = b * QW + min(b, RW);
    const int g1 = g0 + QW + (b < RW ? 1 : 0);

    const float4* __restrict__ p4 = reinterpret_cast<const float4*>(u_pred);
    const float4* __restrict__ o4 = reinterpret_cast<const float4*>(u_obs);

    __shared__ float    sl[THREADS / 32];
    __shared__ float    sh[THREADS / 32];
    __shared__ unsigned s_ticket;

    const int lane = tid & 31;
    const int wid  = tid >> 5;

    int a = g0;
    while (a < g1) {
        const int seg = a / GPS;
        const int e   = min(g1, (seg + 1) * GPS);

        // Per-segment constants
        const float hs  = __ldg(h + seg);
        const float ls  = __ldg(lam + seg);
        const float ts  = __ldg(thresh + seg);
        const float c   = hs * ls * __frcp_rn(1.0f - __expf(-ls)); // h*lam/(1-e^-lam)
        const float omh = 1.0f - hs;
        const float nli = -ls * __frcp_rn(ts);   // exponent = nli * s2
        const float t19 = 19.0f * omh;           // post>0.95 <=> ph > 19*(1-h)

        float slog = 0.0f;
        float shit = 0.0f;

        for (int g = a + tid; g < e; g += THREADS) {
            // 4 rows = 12 floats = 3 float4 per tensor (6 independent LDG.128)
            const float4 pa = __ldg(p4 + 3 * g + 0);
            const float4 pb = __ldg(p4 + 3 * g + 1);
            const float4 pc = __ldg(p4 + 3 * g + 2);
            const float4 oa = __ldg(o4 + 3 * g + 0);
            const float4 ob = __ldg(o4 + 3 * g + 1);
            const float4 oc = __ldg(o4 + 3 * g + 2);

            float s2[4];
            {
                float dx = pa.x - oa.x, dy = pa.y - oa.y, dz = pa.z - oa.z;
                s2[0] = dx * dx + dy * dy + dz * dz;
            }
            {
                float dx = pa.w - oa.w, dy = pb.x - ob.x, dz = pb.y - ob.y;
                s2[1] = dx * dx + dy * dy + dz * dz;
            }
            {
                float dx = pb.z - ob.z, dy = pb.w - ob.w, dz = pc.x - oc.x;
                s2[2] = dx * dx + dy * dy + dz * dz;
            }
            {
                float dx = pc.y - oc.y, dy = pc.z - oc.z, dz = pc.w - oc.w;
                s2[3] = dx * dx + dy * dy + dz * dz;
            }

            float prod = 1.0f;
#pragma unroll
            for (int k = 0; k < 4; ++k) {
                const float s     = s2[k];
                const bool  close = s < ts;
                const float ph    = c * __expf(nli * s);
                const float p     = ph + omh;
                prod *= close ? p : 1.0f;
                const float post = __fdividef(ph, p);
                shit += (close && ph > t19) ? post : 0.0f;
            }
            // log of product of 4 (p in [0.1, 9.1] -> safe fp32 range per iter-chain?
            // take log per iteration to bound the running product):
            slog += __logf(prod);
        }

        // Block reduce slog/shit for this sub-range
#pragma unroll
        for (int off = 16; off > 0; off >>= 1) {
            slog += __shfl_down_sync(0xFFFFFFFFu, slog, off);
            shit += __shfl_down_sync(0xFFFFFFFFu, shit, off);
        }
        if (lane == 0) { sl[wid] = slog; sh[wid] = shit; }
        __syncthreads();
        if (tid == 0) {
            float ta = 0.0f, tb = 0.0f;
#pragma unroll
            for (int i = 0; i < THREADS / 32; ++i) { ta += sl[i]; tb += sh[i]; }
            atomicAdd(&g_acc[seg], ta);
            atomicAdd(&g_acc[SEGS + seg], tb);
        }
        __syncthreads();   // smem reuse safety for the (rare) second sub-range

        a = e;
    }

    // Completion ticket: last block writes output + resets state for graph replay
    __threadfence();
    if (tid == 0) s_ticket = atomicAdd(&g_done, 1u);
    __syncthreads();
    if (s_ticket == NBLK - 1) {
        __threadfence();
        if (tid < SEGS) {
            const float lv = g_acc[tid];
            const float hv = g_acc[SEGS + tid];
            out[tid]            = lv;
            out[SEGS + tid]     = hv;
            out[2 * SEGS + tid] = hv;
            g_acc[tid]        = 0.0f;
            g_acc[SEGS + tid] = 0.0f;
        }
        if (tid == 0) g_done = 0u;
    }
}

extern "C" void kernel_launch(void* const* d_in, const int* in_sizes, int n_in,
                              void* d_out, int out_size) {
    const float* u_pred = (const float*)d_in[0];
    const float* u_obs  = (const float*)d_in[1];
    const float* h      = (const float*)d_in[2];
    const float* lam    = (const float*)d_in[3];
    const float* thresh = (const float*)d_in[4];
    float* out = (float*)d_out;

    trajectory_score_kernel<<<NBLK, THREADS>>>(u_pred, u_obs, h, lam, thresh, out);
}